// round 4
// baseline (speedup 1.0000x reference)
#include <cuda_runtime.h>
#include <stdint.h>

#define NROI    65536
#define NCASC   3
#define NBATCH  64
#define NROWS   (NBATCH * NCASC)
#define SLICES  8
#define SLICE_ELEMS (NROI / SLICES)       // 8192
#define A1_TPB  256
#define A1_WARPS (A1_TPB / 32)
#define ELEMS_PER_WARP (SLICE_ELEMS / A1_WARPS)  // 1024
#define A2_TPB  1024
#define CAP     1024
#define SELCAP  64
#define TPOSC   0.99f
#define TNEGC   0.99f

#define MODE_LIST    0
#define MODE_ALLELIG 1
#define MODE_SLOW    2

struct Keys { uint32_t k0[3]; uint32_t k1[3]; };
struct RowPar { float mx, tk, top2, kth; int nopos, mode; };

// per-row scratch (zeroed by init kernel each call)
__device__ int      g_cp[NROWS];
__device__ int      g_cn[NROWS];
__device__ unsigned g_mxbits[NROWS];
__device__ int      g_poscnt[NROWS];
__device__ int      g_eligcnt[NROWS];
__device__ float    g_posv[NROWS * CAP];
__device__ float    g_negu[NROWS * CAP];
__device__ int      g_negj[NROWS * CAP];
__device__ RowPar   g_par[NROWS];
__device__ int      g_selj[NROWS * SELCAP];
__device__ int      g_selcnt[NROWS];

__device__ const float c_POS_T[3] = {0.6f, 0.7f, 0.8f};
__device__ const float c_IOU_T[3] = {0.2f, 0.3f, 0.4f};
__device__ const float c_NEG_T[3] = {0.3f, 0.3f, 0.3f};

// ---------------------------------------------------------------------------
// JAX threefry2x32 (exact; verified rel_err = 0.0)
// ---------------------------------------------------------------------------
__host__ __device__ __forceinline__ void threefry2x32(
    uint32_t k0, uint32_t k1, uint32_t x0, uint32_t x1,
    uint32_t& o0, uint32_t& o1)
{
    uint32_t ks2 = k0 ^ k1 ^ 0x1BD11BDAu;
    x0 += k0; x1 += k1;
#define TFR(r) { x0 += x1; x1 = (x1 << (r)) | (x1 >> (32 - (r))); x1 ^= x0; }
    TFR(13) TFR(15) TFR(26) TFR(6)  x0 += k1;  x1 += ks2 + 1u;
    TFR(17) TFR(29) TFR(16) TFR(24) x0 += ks2; x1 += k0  + 2u;
    TFR(13) TFR(15) TFR(26) TFR(6)  x0 += k0;  x1 += k1  + 3u;
    TFR(17) TFR(29) TFR(16) TFR(24) x0 += k1;  x1 += ks2 + 4u;
    TFR(13) TFR(15) TFR(26) TFR(6)  x0 += ks2; x1 += k0  + 5u;
#undef TFR
    o0 = x0; o1 = x1;
}

__device__ __forceinline__ float u01(uint32_t k0, uint32_t k1, uint32_t idx)
{
    uint32_t a, c;
    threefry2x32(k0, k1, 0u, idx, a, c);
    uint32_t bits = a ^ c;
    return __uint_as_float((bits >> 9) | 0x3F800000u) - 1.0f;
}

// ---------------------------------------------------------------------------
// Block helpers for the 1024-thread finalize kernel
// ---------------------------------------------------------------------------
__device__ __forceinline__ int block_reduce_sum_int(int v, int* sc)
{
    int tid = threadIdx.x;
    sc[tid] = v; __syncthreads();
    for (int s = A2_TPB / 2; s > 0; s >>= 1) {
        if (tid < s) sc[tid] += sc[tid + s];
        __syncthreads();
    }
    int r = sc[0];
    __syncthreads();
    return r;
}

__device__ void bitonic_desc(float* a)
{
    int tid = threadIdx.x;
    for (int k = 2; k <= A2_TPB; k <<= 1) {
        for (int j = k >> 1; j > 0; j >>= 1) {
            int ixj = tid ^ j;
            if (ixj > tid) {
                float x = a[tid], y = a[ixj];
                bool desc = ((tid & k) == 0);
                if (desc ? (x < y) : (x > y)) { a[tid] = y; a[ixj] = x; }
            }
            __syncthreads();
        }
    }
}

// ---------------------------------------------------------------------------
// Exact fallbacks (statistically never run; guarantee correctness)
// ---------------------------------------------------------------------------
__device__ float kth_bs_iomask(int k, const float* ov, const float* io,
                               float POS_T, int nopos, float mx, int* sc)
{
    unsigned lo = 0u, hi = 0x7F800000u;
    while (hi > lo) {
        unsigned mid = lo + ((hi - lo + 1u) >> 1);
        float t = __uint_as_float(mid);
        int c = 0;
        for (int j = threadIdx.x; j < NROI; j += A2_TPB) {
            float o = ov[j], v = io[j];
            float im = nopos ? ((v >= mx) ? v : 0.0f)
                             : ((o >= POS_T) ? v : 0.0f);
            c += (im >= t);
        }
        c = block_reduce_sum_int(c, sc);
        if (c >= k) lo = mid; else hi = mid - 1u;
    }
    return __uint_as_float(lo);
}

__device__ float kth_bs_score(int k, const float* ov, float NEG_T,
                              uint32_t k0, uint32_t k1, uint32_t rng_base, int* sc)
{
    unsigned lo = 0u, hi = 0x7F800000u;
    while (hi > lo) {
        unsigned mid = lo + ((hi - lo + 1u) >> 1);
        float t = __uint_as_float(mid);
        int c = 0;
        for (int j = threadIdx.x; j < NROI; j += A2_TPB) {
            float o = ov[j];
            if (o <= NEG_T) {
                float u = u01(k0, k1, rng_base + (uint32_t)j);
                c += (u >= t);
            }
        }
        c = block_reduce_sum_int(c, sc);
        if (c >= k) lo = mid; else hi = mid - 1u;
    }
    return __uint_as_float(lo);
}

// ---------------------------------------------------------------------------
// Kernel 0: zero the per-row accumulators (graph replays require reset)
// ---------------------------------------------------------------------------
__global__ void init_kernel()
{
    int r = blockIdx.x * blockDim.x + threadIdx.x;
    if (r < NROWS) {
        g_cp[r] = 0; g_cn[r] = 0;
        g_mxbits[r] = 0u;
        g_poscnt[r] = 0; g_eligcnt[r] = 0;
    }
}

// ---------------------------------------------------------------------------
// Kernel A1: streaming scan. grid = NROWS*SLICES, 256 threads.
// Atomic-free per-warp compaction of eligible indices (register counter),
// then dense threefry over the compacted queue (3.3x fewer hashes).
// ---------------------------------------------------------------------------
__global__ __launch_bounds__(A1_TPB)
void scan_kernel(const float* __restrict__ g_ov,
                 const float* __restrict__ g_io,
                 Keys keys)
{
    __shared__ uint16_t s_q[A1_WARPS][ELEMS_PER_WARP];   // 16 KB
    __shared__ float    s_rmax[A1_TPB];
    __shared__ int      s_rpos[A1_TPB];
    __shared__ int      s_wcnt[A1_WARPS];

    const int tid   = threadIdx.x;
    const int wid   = tid >> 5;
    const int lane  = tid & 31;
    const int r     = blockIdx.x >> 3;
    const int slice = blockIdx.x & (SLICES - 1);
    const int h     = r % 3;
    const int b     = r / 3;

    const float POS_T = c_POS_T[h];
    const float NEG_T = c_NEG_T[h];
    const uint32_t k0 = keys.k0[h];
    const uint32_t k1 = keys.k1[h];
    const uint32_t rng_base = (uint32_t)b * (uint32_t)NROI;

    const float4* ov4 = (const float4*)(g_ov + (size_t)r * NROI) + slice * (SLICE_ELEMS / 4);
    const float4* io4 = (const float4*)(g_io + (size_t)r * NROI) + slice * (SLICE_ELEMS / 4);
    const int j0 = slice * SLICE_ELEMS;

    float lmax = 0.0f;
    int lpos = 0;
    int cnt = 0;                        // warp-uniform eligible count (register)

#pragma unroll
    for (int it = 0; it < SLICE_ELEMS / 4 / A1_TPB; it++) {   // 8 iters
        int q = it * A1_TPB + tid;
        float4 o4 = ov4[q];
        float4 v4 = io4[q];
        int jb = j0 + q * 4;
#pragma unroll
        for (int l = 0; l < 4; l++) {
            float o = (&o4.x)[l];
            float v = (&v4.x)[l];
            lmax = fmaxf(lmax, v);
            bool pm = (o >= POS_T);
            lpos += pm;
            if (pm && v >= TPOSC) {                 // rare (~0.2%): global push
                int p = atomicAdd(&g_cp[r], 1);
                if (p < CAP) g_posv[r * CAP + p] = v;
            }
            bool el = (o <= NEG_T);
            unsigned m = __ballot_sync(0xFFFFFFFFu, el);
            if (el) {
                int off = cnt + __popc(m & ((1u << lane) - 1u));
                s_q[wid][off] = (uint16_t)(jb + l);
            }
            cnt += __popc(m);                       // uniform, no atomics
        }
    }
    __syncwarp();

    // dense threefry over compacted eligible indices
    for (int t = lane; t < cnt; t += 32) {
        int j = (int)s_q[wid][t];
        float u = u01(k0, k1, rng_base + (uint32_t)j);
        if (u >= TNEGC) {                           // rare (~1% of eligible)
            int p = atomicAdd(&g_cn[r], 1);
            if (p < CAP) {
                g_negu[r * CAP + p] = u;
                g_negj[r * CAP + p] = j;
            }
        }
    }

    // block reductions -> global per-row accumulators
    s_rmax[tid] = lmax;
    s_rpos[tid] = lpos;
    if (lane == 0) s_wcnt[wid] = cnt;
    __syncthreads();
    for (int s = A1_TPB / 2; s > 0; s >>= 1) {
        if (tid < s) {
            s_rmax[tid] = fmaxf(s_rmax[tid], s_rmax[tid + s]);
            s_rpos[tid] += s_rpos[tid + s];
        }
        __syncthreads();
    }
    if (tid == 0) {
        int elig = 0;
        for (int w = 0; w < A1_WARPS; w++) elig += s_wcnt[w];
        atomicMax(&g_mxbits[r], __float_as_uint(s_rmax[0]));  // floats >= 0
        atomicAdd(&g_poscnt[r], s_rpos[0]);
        atomicAdd(&g_eligcnt[r], elig);
    }
}

// ---------------------------------------------------------------------------
// Kernel A2: per-row finalize. grid = NROWS, 1024 threads.
// ---------------------------------------------------------------------------
__global__ __launch_bounds__(A2_TPB)
void finalize_kernel(const float* __restrict__ g_ov,
                     const float* __restrict__ g_io,
                     Keys keys)
{
    __shared__ float s_sort[A2_TPB];
    __shared__ int   s_sel;

    const int tid = threadIdx.x;
    const int r = blockIdx.x;
    const int h = r % 3;
    const int b = r / 3;

    const float POS_T = c_POS_T[h];
    const float NEG_T = c_NEG_T[h];
    const float IOU_T = c_IOU_T[h];
    const uint32_t k0 = keys.k0[h];
    const uint32_t k1 = keys.k1[h];
    const uint32_t rng_base = (uint32_t)b * (uint32_t)NROI;

    const float* ov = g_ov + (size_t)r * NROI;
    const float* io = g_io + (size_t)r * NROI;

    const int cp      = g_cp[r];
    const int cn      = g_cn[r];
    const int poscnt  = g_poscnt[r];
    const int eligcnt = g_eligcnt[r];
    const float mx    = __uint_as_float(g_mxbits[r]);

    // -------- positive threshold: 16th (+2nd) largest of iou_masked --------
    int nopos = (poscnt == 0);
    float t16, top2 = 0.0f;
    if (!nopos && cp >= 16 && cp <= CAP) {
        s_sort[tid] = (tid < cp) ? g_posv[r * CAP + tid] : -1.0f;
        __syncthreads();
        bitonic_desc(s_sort);
        t16 = s_sort[15];
        top2 = s_sort[1];
        __syncthreads();
    } else {
        t16 = kth_bs_iomask(16, ov, io, POS_T, nopos, mx, (int*)s_sort);
        if (h == 0) top2 = kth_bs_iomask(2, ov, io, POS_T, nopos, mx, (int*)s_sort);
    }
    float tk = (t16 >= IOU_T) ? t16 : IOU_T;

    // -------- negative threshold: 48th largest random score among eligible --
    float kth = -1.0f;
    int mode;
    int selcnt = 0;
    if (eligcnt < 48) {
        mode = MODE_ALLELIG;                 // kth = -inf: all eligible neg
    } else if (cn >= 48 && cn <= CAP) {
        s_sort[tid] = (tid < cn) ? g_negu[r * CAP + tid] : -1.0f;
        __syncthreads();
        bitonic_desc(s_sort);
        kth = s_sort[47];
        __syncthreads();
        if (tid == 0) s_sel = 0;
        __syncthreads();
        if (tid < cn && g_negu[r * CAP + tid] >= kth) {
            int p = atomicAdd(&s_sel, 1);
            if (p < SELCAP) g_selj[r * SELCAP + p] = g_negj[r * CAP + tid];
        }
        __syncthreads();
        selcnt = s_sel;
        if (selcnt > SELCAP) { mode = MODE_SLOW; selcnt = 0; }  // kth exact
        else mode = MODE_LIST;
    } else {
        mode = MODE_SLOW;
        kth = kth_bs_score(48, ov, NEG_T, k0, k1, rng_base, (int*)s_sort);
    }

    if (tid == 0) {
        g_selcnt[r] = selcnt;
        RowPar p;
        p.mx = mx; p.tk = tk; p.top2 = top2; p.kth = kth;
        p.nopos = nopos; p.mode = mode;
        g_par[r] = p;
    }
}

// ---------------------------------------------------------------------------
// Kernel B: elementwise labels (negatives deferred to kernel C in LIST mode)
// ---------------------------------------------------------------------------
__global__ __launch_bounds__(256)
void label_kernel(const float* __restrict__ g_ov,
                  const float* __restrict__ g_io,
                  const float* __restrict__ g_nm,
                  float* __restrict__ g_out,
                  Keys keys)
{
    int gq = blockIdx.x * 256 + threadIdx.x;       // float4 index
    int r = gq >> 14;                              // 16384 float4 per row
    int h = r % 3;

    RowPar p = g_par[r];
    const float POS_T = c_POS_T[h];
    const float NEG_T = c_NEG_T[h];

    float4 o4 = ((const float4*)g_ov)[gq];
    float4 v4 = ((const float4*)g_io)[gq];
    float4 res;

    int jb = (gq & 16383) * 4;
    uint32_t rng_base = (uint32_t)(r / 3) * (uint32_t)NROI;
    size_t ebase = (size_t)gq * 4;

#pragma unroll
    for (int l = 0; l < 4; l++) {
        float o = (&o4.x)[l];
        float v = (&v4.x)[l];
        float im = p.nopos ? ((v >= p.mx) ? v : 0.0f)
                           : ((o >= POS_T) ? v : 0.0f);
        bool posb = (im >= p.tk);
        if (h == 0) posb = posb || (im > p.top2);
        float posf = 0.0f;
        if (posb) posf = g_nm[ebase + l];          // rare scalar load

        float negf = 0.0f;
        if (p.mode == MODE_ALLELIG) {
            negf = (o <= NEG_T) ? 1.0f : 0.0f;
        } else if (p.mode == MODE_SLOW) {
            if (o <= NEG_T) {
                float u = u01(keys.k0[h], keys.k1[h],
                              rng_base + (uint32_t)(jb + l));
                if (u >= p.kth) negf = 1.0f;
            }
        }
        (&res.x)[l] = (-1.0f + negf) + 2.0f * posf;
    }
    ((float4*)g_out)[gq] = res;
}

// ---------------------------------------------------------------------------
// Kernel C: scatter-overwrite selected negatives (LIST mode only)
// ---------------------------------------------------------------------------
__global__ void scatter_kernel(const float* __restrict__ g_ov,
                               const float* __restrict__ g_io,
                               const float* __restrict__ g_nm,
                               float* __restrict__ g_out)
{
    int r = blockIdx.x;
    int h = r % 3;
    RowPar p = g_par[r];
    int cnt = g_selcnt[r];
    const float POS_T = c_POS_T[h];
    size_t rowoff = (size_t)r * NROI;

    for (int i = threadIdx.x; i < cnt; i += blockDim.x) {
        int j = g_selj[r * SELCAP + i];
        float o = g_ov[rowoff + j];
        float v = g_io[rowoff + j];
        float im = p.nopos ? ((v >= p.mx) ? v : 0.0f)
                           : ((o >= POS_T) ? v : 0.0f);
        bool posb = (im >= p.tk);
        if (h == 0) posb = posb || (im > p.top2);
        float posf = 0.0f;
        if (posb) posf = g_nm[rowoff + j];
        g_out[rowoff + j] = 2.0f * posf;           // -1 + 1 + 2*pos
    }
}

// ---------------------------------------------------------------------------
// Launch
// ---------------------------------------------------------------------------
extern "C" void kernel_launch(void* const* d_in, const int* in_sizes, int n_in,
                              void* d_out, int out_size)
{
    const float* ov = (const float*)d_in[0];
    const float* io = (const float*)d_in[1];
    const float* nm = (const float*)d_in[2];
    float* out = (float*)d_out;

    Keys keys;
    for (int h = 0; h < NCASC; h++) {
        uint32_t a, c;
        threefry2x32(0u, 42u, 0u, (uint32_t)h, a, c);
        keys.k0[h] = a;
        keys.k1[h] = c;
    }

    init_kernel<<<1, NROWS>>>();
    scan_kernel<<<NROWS * SLICES, A1_TPB>>>(ov, io, keys);
    finalize_kernel<<<NROWS, A2_TPB>>>(ov, io, keys);
    label_kernel<<<(NROWS * (NROI / 4)) / 256, 256>>>(ov, io, nm, out, keys);
    scatter_kernel<<<NROWS, 64>>>(ov, io, nm, out);
}